// round 1
// baseline (speedup 1.0000x reference)
#include <cuda_runtime.h>
#include <math.h>

// Problem dims
#define B2   2
#define L_   2048
#define DM_  1024
#define DI_  2048
#define NS_  16
#define RR_  64
#define ML_  (B2 * L_)          // 4096 rows
#define XZW  (2 * DI_)          // 4096
#define XDW  (RR_ + 2 * NS_)    // 96

// ---------------- scratch (device globals; allocation-free) ----------------
__device__ float g_h[(size_t)ML_ * DM_];            // rmsnorm output      16.8 MB
__device__ float g_xz[(size_t)ML_ * XZW];           // in_proj output      67 MB
__device__ float g_u[(size_t)ML_ * DI_];            // conv+silu output    33.5 MB
__device__ float g_xdbl[(size_t)ML_ * XDW];         // x_proj output       1.6 MB
__device__ float g_dt[(size_t)ML_ * DI_];           // softplus(dt)        33.5 MB
__device__ float g_y[(size_t)ML_ * DI_];            // scan output         33.5 MB
__device__ float g_yg[(size_t)ML_ * DI_];           // gated y             33.5 MB

// ---------------- RMSNorm ----------------
__global__ void __launch_bounds__(256) rmsnorm_kernel(const float* __restrict__ x,
                                                      const float* __restrict__ w) {
    int row = blockIdx.x;
    int tid = threadIdx.x;
    const float4* xr = (const float4*)(x + (size_t)row * DM_);
    float4 v = xr[tid];                    // 256 threads * 4 = 1024
    float ss = v.x * v.x + v.y * v.y + v.z * v.z + v.w * v.w;
    #pragma unroll
    for (int o = 16; o > 0; o >>= 1) ss += __shfl_xor_sync(0xffffffffu, ss, o);
    __shared__ float sm[8];
    if ((tid & 31) == 0) sm[tid >> 5] = ss;
    __syncthreads();
    float tot = sm[0] + sm[1] + sm[2] + sm[3] + sm[4] + sm[5] + sm[6] + sm[7];
    float s = rsqrtf(tot * (1.0f / DM_) + 1e-5f);
    const float4* wr = (const float4*)w;
    float4 wv = wr[tid];
    float4 o;
    o.x = v.x * s * wv.x; o.y = v.y * s * wv.y; o.z = v.z * s * wv.z; o.w = v.w * s * wv.w;
    ((float4*)(g_h + (size_t)row * DM_))[tid] = o;
}

// ---------------- generic 128x128x8 SGEMM with epilogue modes ----------------
// mode 0: C = acc
// mode 1: C = softplus(acc + e1[col])        (dt projection)
// mode 2: C = acc + e1[row*ldc + col]        (out_proj + residual x)
__global__ void __launch_bounds__(256) sgemm128(
    const float* __restrict__ A, const float* __restrict__ B, float* __restrict__ C,
    int M, int N, int K, int lda, int ldb, int ldc,
    int mode, const float* __restrict__ e1)
{
    __shared__ float As[8][128];
    __shared__ float Bs[8][128];
    int tid = threadIdx.x;
    int tx = tid & 15, ty = tid >> 4;
    const float* Ab = A + (size_t)blockIdx.y * 128 * lda;
    const float* Bb = B + blockIdx.x * 128;
    int aRow = tid >> 1, aCol = (tid & 1) * 4;
    int bRow = tid >> 5, bCol = (tid & 31) * 4;

    float4 av = *(const float4*)(Ab + (size_t)aRow * lda + aCol);
    float4 bv = *(const float4*)(Bb + (size_t)bRow * ldb + bCol);
    float acc[8][8] = {};

    int k0 = 0;
    for (;;) {
        As[aCol + 0][aRow] = av.x; As[aCol + 1][aRow] = av.y;
        As[aCol + 2][aRow] = av.z; As[aCol + 3][aRow] = av.w;
        *(float4*)&Bs[bRow][bCol] = bv;
        __syncthreads();
        k0 += 8;
        if (k0 < K) {
            av = *(const float4*)(Ab + (size_t)aRow * lda + k0 + aCol);
            bv = *(const float4*)(Bb + (size_t)(k0 + bRow) * ldb + bCol);
        }
        #pragma unroll
        for (int kk = 0; kk < 8; kk++) {
            float ra[8], rb[8];
            *(float4*)(ra)     = *(const float4*)&As[kk][ty * 8];
            *(float4*)(ra + 4) = *(const float4*)&As[kk][ty * 8 + 4];
            *(float4*)(rb)     = *(const float4*)&Bs[kk][tx * 8];
            *(float4*)(rb + 4) = *(const float4*)&Bs[kk][tx * 8 + 4];
            #pragma unroll
            for (int i = 0; i < 8; i++)
                #pragma unroll
                for (int j = 0; j < 8; j++)
                    acc[i][j] = fmaf(ra[i], rb[j], acc[i][j]);
        }
        if (k0 >= K) break;
        __syncthreads();
    }

    int row0 = blockIdx.y * 128 + ty * 8;
    int col0 = blockIdx.x * 128 + tx * 8;
    #pragma unroll
    for (int i = 0; i < 8; i++) {
        #pragma unroll
        for (int j = 0; j < 8; j++) {
            float v = acc[i][j];
            if (mode == 1) {
                v += e1[col0 + j];
                // numerically stable softplus (matches jax.nn.softplus)
                v = (v > 0.f) ? (v + log1pf(expf(-v))) : log1pf(expf(v));
            } else if (mode == 2) {
                v += e1[(size_t)(row0 + i) * ldc + col0 + j];
            }
            C[(size_t)(row0 + i) * ldc + col0 + j] = v;
        }
    }
}

// ---------------- causal depthwise conv (K=4) + bias + SiLU ----------------
__global__ void __launch_bounds__(256) conv_silu_kernel(const float* __restrict__ conv_w,
                                                        const float* __restrict__ conv_b) {
    int idx = blockIdx.x * 256 + threadIdx.x;      // over ML_*DI_
    int d = idx & (DI_ - 1);
    int row = idx >> 11;                            // /DI_
    int t = row & (L_ - 1);
    float w0 = conv_w[d * 4 + 0], w1 = conv_w[d * 4 + 1];
    float w2 = conv_w[d * 4 + 2], w3 = conv_w[d * 4 + 3];
    const float* base = g_xz + (size_t)row * XZW + d;   // u = first half of xz
    float acc = conv_b[d] + base[0] * w3;
    if (t >= 1) acc = fmaf(base[-(ptrdiff_t)XZW], w2, acc);
    if (t >= 2) acc = fmaf(base[-2 * (ptrdiff_t)XZW], w1, acc);
    if (t >= 3) acc = fmaf(base[-3 * (ptrdiff_t)XZW], w0, acc);
    g_u[idx] = acc / (1.f + __expf(-acc));          // silu
}

// ---------------- x_proj GEMM: [4096 x 2048] @ [2048 x 96] -> g_xdbl --------
// BM=32, BN=96 (full), BK=16; 256 threads (16x16), micro 2x6
__global__ void __launch_bounds__(256) gemm_xproj(const float* __restrict__ Bw) {
    __shared__ float As[16][32];
    __shared__ float Bs[16][96];
    int tid = threadIdx.x;
    int tx = tid & 15, ty = tid >> 4;
    const float* Ab = g_u + (size_t)blockIdx.x * 32 * DI_;
    float acc[2][6] = {};
    for (int k0 = 0; k0 < DI_; k0 += 16) {
        if (tid < 128) {
            int aRow = tid >> 2, aCol = (tid & 3) * 4;
            float4 av = *(const float4*)(Ab + (size_t)aRow * DI_ + k0 + aCol);
            As[aCol + 0][aRow] = av.x; As[aCol + 1][aRow] = av.y;
            As[aCol + 2][aRow] = av.z; As[aCol + 3][aRow] = av.w;
        }
        #pragma unroll
        for (int i = 0; i < 6; i++) {
            int idx = tid + 256 * i;
            int r = idx / 96, c = idx - r * 96;
            Bs[r][c] = Bw[(size_t)(k0 + r) * 96 + c];
        }
        __syncthreads();
        #pragma unroll
        for (int kk = 0; kk < 16; kk++) {
            float a0 = As[kk][ty * 2], a1 = As[kk][ty * 2 + 1];
            #pragma unroll
            for (int j = 0; j < 6; j++) {
                float bj = Bs[kk][tx * 6 + j];
                acc[0][j] = fmaf(a0, bj, acc[0][j]);
                acc[1][j] = fmaf(a1, bj, acc[1][j]);
            }
        }
        __syncthreads();
    }
    int row0 = blockIdx.x * 32 + ty * 2;
    #pragma unroll
    for (int i = 0; i < 2; i++)
        #pragma unroll
        for (int j = 0; j < 6; j++)
            g_xdbl[(size_t)(row0 + i) * 96 + tx * 6 + j] = acc[i][j];
}

// ---------------- selective scan ----------------
// lane n in 0..15 owns state n of channel (b,d); 2 channels per warp.
// grid = B2 * DI_/16 = 256 blocks, 256 threads (16 channels/block).
__global__ void __launch_bounds__(256) scan_kernel(const float* __restrict__ A_log) {
    int tid = threadIdx.x;
    int lane = tid & 31;
    int n = lane & 15;
    int ch = tid >> 4;                       // 0..15
    int b = blockIdx.x >> 7;                 // /128
    int d = ((blockIdx.x & 127) << 4) + ch;
    float A_n = -expf(A_log[d * NS_ + n]);
    float hst = 0.f;
    const float* dtp = g_dt + (size_t)b * L_ * DI_ + d;
    const float* up  = g_u  + (size_t)b * L_ * DI_ + d;
    const float* xb  = g_xdbl + (size_t)b * L_ * XDW;
    float* yp = g_y + (size_t)b * L_ * DI_ + d;
    #pragma unroll 2
    for (int t = 0; t < L_; t++) {
        float dt_v = __ldg(dtp + (size_t)t * DI_);
        float u_v  = __ldg(up  + (size_t)t * DI_);
        float Bn = __ldg(xb + t * XDW + RR_ + n);
        float Cn = __ldg(xb + t * XDW + RR_ + NS_ + n);
        float dA = __expf(dt_v * A_n);
        hst = fmaf(dA, hst, dt_v * u_v * Bn);
        float p = hst * Cn;
        p += __shfl_xor_sync(0xffffffffu, p, 8);
        p += __shfl_xor_sync(0xffffffffu, p, 4);
        p += __shfl_xor_sync(0xffffffffu, p, 2);
        p += __shfl_xor_sync(0xffffffffu, p, 1);
        if (n == 0) yp[(size_t)t * DI_] = p;
    }
}

// ---------------- gating: yg = (y + u*D) * silu(z) ----------------
__global__ void __launch_bounds__(256) gate_kernel(const float* __restrict__ Dw) {
    int idx = blockIdx.x * 256 + threadIdx.x;
    int d = idx & (DI_ - 1);
    int row = idx >> 11;
    float z = g_xz[(size_t)row * XZW + DI_ + d];
    float sz = z / (1.f + __expf(-z));
    g_yg[idx] = (g_y[idx] + g_u[idx] * Dw[d]) * sz;
}

// ---------------- launch ----------------
extern "C" void kernel_launch(void* const* d_in, const int* in_sizes, int n_in,
                              void* d_out, int out_size) {
    (void)in_sizes; (void)n_in; (void)out_size;
    const float* x          = (const float*)d_in[0];
    // d_in[1] hormone_vectors unused
    const float* norm_w     = (const float*)d_in[2];
    const float* in_proj_w  = (const float*)d_in[3];
    const float* conv_w     = (const float*)d_in[4];
    const float* conv_b     = (const float*)d_in[5];
    const float* x_proj_w   = (const float*)d_in[6];
    const float* dt_proj_w  = (const float*)d_in[7];
    const float* dt_proj_b  = (const float*)d_in[8];
    const float* A_log      = (const float*)d_in[9];
    const float* Dw         = (const float*)d_in[10];
    const float* out_proj_w = (const float*)d_in[11];
    float* out = (float*)d_out;

    float *p_h, *p_xz, *p_xdbl, *p_dt, *p_yg;
    cudaGetSymbolAddress((void**)&p_h, g_h);
    cudaGetSymbolAddress((void**)&p_xz, g_xz);
    cudaGetSymbolAddress((void**)&p_xdbl, g_xdbl);
    cudaGetSymbolAddress((void**)&p_dt, g_dt);
    cudaGetSymbolAddress((void**)&p_yg, g_yg);

    // 1) h = rmsnorm(x) * norm_w
    rmsnorm_kernel<<<ML_, 256>>>(x, norm_w);
    // 2) xz = h @ in_proj_w      [4096 x 4096], K=1024
    sgemm128<<<dim3(XZW / 128, ML_ / 128), 256>>>(p_h, in_proj_w, p_xz,
        ML_, XZW, DM_, DM_, XZW, XZW, 0, nullptr);
    // 3) u = silu(causal_conv(xz[:, :2048]) + b)
    conv_silu_kernel<<<(ML_ * DI_) / 256, 256>>>(conv_w, conv_b);
    // 4) xdbl = u @ x_proj_w     [4096 x 96], K=2048
    gemm_xproj<<<ML_ / 32, 256>>>(x_proj_w);
    // 5) dt = softplus(xdbl[:, :64] @ dt_proj_w + b)   [4096 x 2048], K=64
    sgemm128<<<dim3(DI_ / 128, ML_ / 128), 256>>>(p_xdbl, dt_proj_w, p_dt,
        ML_, DI_, RR_, XDW, DI_, DI_, 1, dt_proj_b);
    // 6) selective scan -> y
    scan_kernel<<<B2 * (DI_ / 16), 256>>>(A_log);
    // 7) yg = (y + u*D) * silu(z)
    gate_kernel<<<(ML_ * DI_) / 256, 256>>>(Dw);
    // 8) out = yg @ out_proj_w + x   [4096 x 1024], K=2048
    sgemm128<<<dim3(DM_ / 128, ML_ / 128), 256>>>(p_yg, out_proj_w, out,
        ML_, DM_, DI_, DI_, DM_, DM_, 2, x);
}

// round 3
// speedup vs baseline: 1.9583x; 1.9583x over previous
#include <cuda_runtime.h>
#include <cuda_bf16.h>
#include <math.h>
#include <stdint.h>

// ---------------- dims ----------------
#define B2   2
#define L_   2048
#define DM_  1024
#define DI_  2048
#define NS_  16
#define RR_  64
#define ML_  (B2 * L_)          // 4096
#define XZW  (2 * DI_)          // 4096
#define XDP  128                // padded xdbl width (96 -> 128)

// ---------------- scratch (device globals) ----------------
__device__ float g_xz  [(size_t)ML_ * XZW];
__device__ float g_u   [(size_t)ML_ * DI_];
__device__ float g_xdbl[(size_t)ML_ * XDP];
__device__ float g_dt  [(size_t)ML_ * DI_];
__device__ float g_y   [(size_t)ML_ * DI_];
__device__ __nv_bfloat16 g_hb   [(size_t)ML_ * DM_];
__device__ __nv_bfloat16 g_ub   [(size_t)ML_ * DI_];
__device__ __nv_bfloat16 g_ygb  [(size_t)ML_ * DI_];
__device__ __nv_bfloat16 g_dtrb [(size_t)ML_ * RR_];
__device__ __nv_bfloat16 g_w_in [(size_t)XZW * DM_];   // [4096,1024]
__device__ __nv_bfloat16 g_w_xp [(size_t)XDP * DI_];   // [128,2048] rows 96..127 zero
__device__ __nv_bfloat16 g_w_dt [(size_t)DI_ * RR_];   // [2048,64]
__device__ __nv_bfloat16 g_w_out[(size_t)DM_ * DI_];   // [1024,2048]

// ---------------- asm helpers ----------------
__device__ __forceinline__ uint32_t smem_u32(const void* p) {
    uint32_t a;
    asm("{ .reg .u64 t; cvta.to.shared.u64 t, %1; cvt.u32.u64 %0, t; }" : "=r"(a) : "l"(p));
    return a;
}
#define LDSM4(R0, R1, R2, R3, ADDR) \
    asm volatile("ldmatrix.sync.aligned.m8n8.x4.shared.b16 {%0,%1,%2,%3}, [%4];" \
        : "=r"(R0), "=r"(R1), "=r"(R2), "=r"(R3) : "r"(ADDR))
#define MMA16816(D, A0, A1, A2, A3, B0, B1) \
    asm volatile("mma.sync.aligned.m16n8k16.row.col.f32.bf16.bf16.f32 " \
        "{%0,%1,%2,%3}, {%4,%5,%6,%7}, {%8,%9}, {%0,%1,%2,%3};" \
        : "+f"((D)[0]), "+f"((D)[1]), "+f"((D)[2]), "+f"((D)[3]) \
        : "r"(A0), "r"(A1), "r"(A2), "r"(A3), "r"(B0), "r"(B1))
#define CP16(S, G) \
    asm volatile("cp.async.cg.shared.global [%0], [%1], 16;" :: "r"(S), "l"(G))
#define CPCOMMIT() asm volatile("cp.async.commit_group;")

// smem layout: stage s (0/1) at s*20480; A tile at +0 (128 rows x 80B), B tile at +10240
#define STAGE_BYTES 20480
#define ROW_B 80

// ---------------- bf16 HMMA GEMM: C[M,N] = A[M,K] @ Bt[N,K]^T ----------------
// 128x128 tile, BK=32. 256 thr = 8 warps (4 over M x 2 over N), warp tile 32x64.
// mode 0: C = acc ; 1: C = softplus(acc + e1[col]) ; 2: C = acc + e1[row*ldN + col]
__global__ void __launch_bounds__(256) hmma_gemm(
    const __nv_bfloat16* __restrict__ A, const __nv_bfloat16* __restrict__ Bt,
    float* __restrict__ C, int K, int ldc, int mode, const float* __restrict__ e1)
{
    __shared__ __align__(128) char smem[2 * STAGE_BYTES];
    uint32_t sb = smem_u32(smem);
    int tid = threadIdx.x, wid = tid >> 5, lane = tid & 31;
    int row0 = blockIdx.y * 128, col0 = blockIdx.x * 128;
    int m0 = (wid & 3) * 32, n0 = (wid >> 2) * 64;

    // cp.async chunks: chunk c -> row=c>>2, q=c&3 (16B each); thread does c=tid, tid+256
    int rA0 = tid >> 2, q0 = tid & 3;
    int rA1 = (tid + 256) >> 2, q1 = tid & 3;
    const char* gA0 = (const char*)(A  + (size_t)(row0 + rA0) * K + q0 * 8);
    const char* gA1 = (const char*)(A  + (size_t)(row0 + rA1) * K + q1 * 8);
    const char* gB0 = (const char*)(Bt + (size_t)(col0 + rA0) * K + q0 * 8);
    const char* gB1 = (const char*)(Bt + (size_t)(col0 + rA1) * K + q1 * 8);
    uint32_t sA0 = sb + rA0 * ROW_B + q0 * 16;
    uint32_t sA1 = sb + rA1 * ROW_B + q1 * 16;
    uint32_t sB0 = sA0 + 10240;
    uint32_t sB1 = sA1 + 10240;

    // ldmatrix lane bases
    uint32_t aBase = sb + (m0 + (lane & 15)) * ROW_B + ((lane >> 4) << 4);
    uint32_t bBase = sb + 10240 + (n0 + (lane & 15)) * ROW_B + ((lane >> 4) << 4);

    float acc[2][8][4];
    #pragma unroll
    for (int i = 0; i < 2; i++)
        #pragma unroll
        for (int j = 0; j < 8; j++)
            #pragma unroll
            for (int v = 0; v < 4; v++) acc[i][j][v] = 0.f;

    const int NK = K >> 5;
    // issue stage 0
    {
        CP16(sA0, gA0); CP16(sA1, gA1); CP16(sB0, gB0); CP16(sB1, gB1);
        CPCOMMIT();
    }
    for (int kt = 0; kt < NK; kt++) {
        if (kt + 1 < NK) {
            uint32_t so = ((kt + 1) & 1) * STAGE_BYTES;
            size_t go = (size_t)(kt + 1) * 64;   // 32 bf16 = 64B
            CP16(sA0 + so, gA0 + go); CP16(sA1 + so, gA1 + go);
            CP16(sB0 + so, gB0 + go); CP16(sB1 + so, gB1 + go);
            CPCOMMIT();
            asm volatile("cp.async.wait_group 1;");
        } else {
            asm volatile("cp.async.wait_group 0;");
        }
        __syncthreads();

        uint32_t so = (kt & 1) * STAGE_BYTES;
        #pragma unroll
        for (int s = 0; s < 2; s++) {
            uint32_t a[2][4], b[4][4];
            #pragma unroll
            for (int mt = 0; mt < 2; mt++)
                LDSM4(a[mt][0], a[mt][1], a[mt][2], a[mt][3],
                      aBase + so + s * 32 + mt * (16 * ROW_B));
            #pragma unroll
            for (int g = 0; g < 4; g++)
                LDSM4(b[g][0], b[g][1], b[g][2], b[g][3],
                      bBase + so + s * 32 + g * (16 * ROW_B));
            #pragma unroll
            for (int mt = 0; mt < 2; mt++)
                #pragma unroll
                for (int j = 0; j < 8; j++) {
                    int g = j >> 1, o = j & 1;
                    MMA16816(acc[mt][j], a[mt][0], a[mt][1], a[mt][2], a[mt][3],
                             b[g][o], b[g][o + 2]);
                }
        }
        __syncthreads();
    }

    // epilogue
    #pragma unroll
    for (int mt = 0; mt < 2; mt++) {
        #pragma unroll
        for (int j = 0; j < 8; j++) {
            int r_ = row0 + m0 + mt * 16 + (lane >> 2);
            int c_ = col0 + n0 + j * 8 + (lane & 3) * 2;
            #pragma unroll
            for (int h = 0; h < 2; h++) {      // h=0: rows r_, h=1: rows r_+8
                float v0 = acc[mt][j][h * 2], v1 = acc[mt][j][h * 2 + 1];
                int rr = r_ + h * 8;
                if (mode == 1) {
                    v0 += e1[c_];
                    v1 += e1[c_ + 1];
                    v0 = fmaxf(v0, 0.f) + __logf(1.f + __expf(-fabsf(v0)));
                    v1 = fmaxf(v1, 0.f) + __logf(1.f + __expf(-fabsf(v1)));
                } else if (mode == 2) {
                    const float2 xv = *(const float2*)(e1 + (size_t)rr * ldc + c_);
                    v0 += xv.x; v1 += xv.y;
                }
                *(float2*)(C + (size_t)rr * ldc + c_) = make_float2(v0, v1);
            }
        }
    }
}

// ---------------- transpose fp32 [K,Nin] -> bf16 [Nout,K] (zero-pad) ----------------
__global__ void transpose_bf16(const float* __restrict__ in, __nv_bfloat16* __restrict__ out,
                               int K, int Nin, int Nout) {
    __shared__ float tile[32][33];
    int kb = blockIdx.x * 32, nb = blockIdx.y * 32;
    int tx = threadIdx.x, ty = threadIdx.y;   // 32 x 8
    #pragma unroll
    for (int i = 0; i < 32; i += 8) {
        int k = kb + ty + i, n = nb + tx;
        tile[ty + i][tx] = (n < Nin) ? in[(size_t)k * Nin + n] : 0.f;
    }
    __syncthreads();
    #pragma unroll
    for (int i = 0; i < 32; i += 8) {
        int n = nb + ty + i, k = kb + tx;
        out[(size_t)n * K + k] = __float2bfloat16(tile[tx][ty + i]);
    }
}

// ---------------- RMSNorm -> bf16 ----------------
__global__ void __launch_bounds__(256) rmsnorm_kernel(const float* __restrict__ x,
                                                      const float* __restrict__ w) {
    int row = blockIdx.x;
    int tid = threadIdx.x;
    float4 v = ((const float4*)(x + (size_t)row * DM_))[tid];
    float ss = v.x * v.x + v.y * v.y + v.z * v.z + v.w * v.w;
    #pragma unroll
    for (int o = 16; o > 0; o >>= 1) ss += __shfl_xor_sync(0xffffffffu, ss, o);
    __shared__ float sm[8];
    if ((tid & 31) == 0) sm[tid >> 5] = ss;
    __syncthreads();
    float tot = sm[0] + sm[1] + sm[2] + sm[3] + sm[4] + sm[5] + sm[6] + sm[7];
    float s = rsqrtf(tot * (1.0f / DM_) + 1e-5f);
    float4 wv = ((const float4*)w)[tid];
    __nv_bfloat162* op = (__nv_bfloat162*)(g_hb + (size_t)row * DM_);
    op[tid * 2]     = __floats2bfloat162_rn(v.x * s * wv.x, v.y * s * wv.y);
    op[tid * 2 + 1] = __floats2bfloat162_rn(v.z * s * wv.z, v.w * s * wv.w);
}

// ---------------- causal depthwise conv (K=4) + bias + SiLU ----------------
__global__ void __launch_bounds__(256) conv_silu_kernel(const float* __restrict__ conv_w,
                                                        const float* __restrict__ conv_b) {
    int idx = blockIdx.x * 256 + threadIdx.x;
    int d = idx & (DI_ - 1);
    int row = idx >> 11;
    int t = row & (L_ - 1);
    float w0 = conv_w[d * 4 + 0], w1 = conv_w[d * 4 + 1];
    float w2 = conv_w[d * 4 + 2], w3 = conv_w[d * 4 + 3];
    const float* base = g_xz + (size_t)row * XZW + d;
    float acc = conv_b[d] + base[0] * w3;
    if (t >= 1) acc = fmaf(base[-(ptrdiff_t)XZW], w2, acc);
    if (t >= 2) acc = fmaf(base[-2 * (ptrdiff_t)XZW], w1, acc);
    if (t >= 3) acc = fmaf(base[-3 * (ptrdiff_t)XZW], w0, acc);
    float u = acc / (1.f + __expf(-acc));
    g_u[idx] = u;
    g_ub[idx] = __float2bfloat16(u);
}

// ---------------- extract bf16 dt_r from padded xdbl ----------------
__global__ void __launch_bounds__(256) dtr_kernel() {
    int idx = blockIdx.x * 256 + threadIdx.x;   // ML_*RR_
    int i = idx >> 6, j = idx & 63;
    g_dtrb[idx] = __float2bfloat16(g_xdbl[(size_t)i * XDP + j]);
}

// ---------------- selective scan ----------------
__global__ void __launch_bounds__(256) scan_kernel(const float* __restrict__ A_log) {
    int tid = threadIdx.x;
    int lane = tid & 31;
    int n = lane & 15;
    int ch = tid >> 4;
    int b = blockIdx.x >> 7;
    int d = ((blockIdx.x & 127) << 4) + ch;
    float A_n = -expf(A_log[d * NS_ + n]);
    float hst = 0.f;
    const float* dtp = g_dt + (size_t)b * L_ * DI_ + d;
    const float* up  = g_u  + (size_t)b * L_ * DI_ + d;
    const float* xb  = g_xdbl + (size_t)b * L_ * XDP;
    float* yp = g_y + (size_t)b * L_ * DI_ + d;
    #pragma unroll 2
    for (int t = 0; t < L_; t++) {
        float dt_v = __ldg(dtp + (size_t)t * DI_);
        float u_v  = __ldg(up  + (size_t)t * DI_);
        float Bn = __ldg(xb + t * XDP + RR_ + n);
        float Cn = __ldg(xb + t * XDP + RR_ + NS_ + n);
        float dA = __expf(dt_v * A_n);
        hst = fmaf(dA, hst, dt_v * u_v * Bn);
        float p = hst * Cn;
        p += __shfl_xor_sync(0xffffffffu, p, 8);
        p += __shfl_xor_sync(0xffffffffu, p, 4);
        p += __shfl_xor_sync(0xffffffffu, p, 2);
        p += __shfl_xor_sync(0xffffffffu, p, 1);
        if (n == 0) yp[(size_t)t * DI_] = p;
    }
}

// ---------------- gating: ygb = bf16((y + u*D) * silu(z)) ----------------
__global__ void __launch_bounds__(256) gate_kernel(const float* __restrict__ Dw) {
    int idx = blockIdx.x * 256 + threadIdx.x;
    int d = idx & (DI_ - 1);
    int row = idx >> 11;
    float z = g_xz[(size_t)row * XZW + DI_ + d];
    float sz = z / (1.f + __expf(-z));
    g_ygb[idx] = __float2bfloat16((g_y[idx] + g_u[idx] * Dw[d]) * sz);
}

// ---------------- launch ----------------
extern "C" void kernel_launch(void* const* d_in, const int* in_sizes, int n_in,
                              void* d_out, int out_size) {
    (void)in_sizes; (void)n_in; (void)out_size;
    const float* x          = (const float*)d_in[0];
    const float* norm_w     = (const float*)d_in[2];
    const float* in_proj_w  = (const float*)d_in[3];
    const float* conv_w     = (const float*)d_in[4];
    const float* conv_b     = (const float*)d_in[5];
    const float* x_proj_w   = (const float*)d_in[6];
    const float* dt_proj_w  = (const float*)d_in[7];
    const float* dt_proj_b  = (const float*)d_in[8];
    const float* A_log      = (const float*)d_in[9];
    const float* Dw         = (const float*)d_in[10];
    const float* out_proj_w = (const float*)d_in[11];
    float* out = (float*)d_out;

    float *p_xz, *p_xdbl, *p_dt;
    __nv_bfloat16 *p_hb, *p_ub, *p_ygb, *p_dtrb, *p_w_in, *p_w_xp, *p_w_dt, *p_w_out;
    cudaGetSymbolAddress((void**)&p_xz, g_xz);
    cudaGetSymbolAddress((void**)&p_xdbl, g_xdbl);
    cudaGetSymbolAddress((void**)&p_dt, g_dt);
    cudaGetSymbolAddress((void**)&p_hb, g_hb);
    cudaGetSymbolAddress((void**)&p_ub, g_ub);
    cudaGetSymbolAddress((void**)&p_ygb, g_ygb);
    cudaGetSymbolAddress((void**)&p_dtrb, g_dtrb);
    cudaGetSymbolAddress((void**)&p_w_in, g_w_in);
    cudaGetSymbolAddress((void**)&p_w_xp, g_w_xp);
    cudaGetSymbolAddress((void**)&p_w_dt, g_w_dt);
    cudaGetSymbolAddress((void**)&p_w_out, g_w_out);

    dim3 tb(32, 8);
    transpose_bf16<<<dim3(DM_ / 32, XZW / 32), tb>>>(in_proj_w, p_w_in, DM_, XZW, XZW);
    transpose_bf16<<<dim3(DI_ / 32, XDP / 32), tb>>>(x_proj_w, p_w_xp, DI_, 96, XDP);
    transpose_bf16<<<dim3(RR_ / 32, DI_ / 32), tb>>>(dt_proj_w, p_w_dt, RR_, DI_, DI_);
    transpose_bf16<<<dim3(DI_ / 32, DM_ / 32), tb>>>(out_proj_w, p_w_out, DI_, DM_, DM_);

    // 1) h = rmsnorm(x) -> bf16
    rmsnorm_kernel<<<ML_, 256>>>(x, norm_w);
    // 2) xz = h @ in_proj_w   [4096 x 4096], K=1024
    hmma_gemm<<<dim3(XZW / 128, ML_ / 128), 256>>>(p_hb, p_w_in, p_xz, DM_, XZW, 0, nullptr);
    // 3) u = silu(conv(xz[:, :2048]) + b)
    conv_silu_kernel<<<(ML_ * DI_) / 256, 256>>>(conv_w, conv_b);
    // 4) xdbl = u @ x_proj_w  [4096 x 128(pad)], K=2048
    hmma_gemm<<<dim3(1, ML_ / 128), 256>>>(p_ub, p_w_xp, p_xdbl, DI_, XDP, 0, nullptr);
    // 5) dt_r -> bf16
    dtr_kernel<<<(ML_ * RR_) / 256, 256>>>();
    // 6) dt = softplus(dt_r @ dt_proj_w + b)  [4096 x 2048], K=64
    hmma_gemm<<<dim3(DI_ / 128, ML_ / 128), 256>>>(p_dtrb, p_w_dt, p_dt, RR_, DI_, 1, dt_proj_b);
    // 7) selective scan
    scan_kernel<<<B2 * (DI_ / 16), 256>>>(A_log);
    // 8) gating -> bf16
    gate_kernel<<<(ML_ * DI_) / 256, 256>>>(Dw);
    // 9) out = yg @ out_proj_w + x  [4096 x 1024], K=2048
    hmma_gemm<<<dim3(DM_ / 128, ML_ / 128), 256>>>(p_ygb, p_w_out, out, DI_, DM_, 2, x);
}